// round 14
// baseline (speedup 1.0000x reference)
#include <cuda_runtime.h>
#include <cuda_bf16.h>
#include <cstdint>

#define NROWS  65536
#define DIM    128
#define KCB    1024
#define NCHUNK 16
#define NTILES 512
#define TAU    1.5e-4f

// ---------------- device scratch (no allocations allowed) ----------------
__device__ float              g_csum2[KCB];
__device__ int                g_counts[KCB];
__device__ double             g_loss;
__device__ unsigned long long g_best[NROWS];
__device__ int                g_nrescue;
__device__ int                g_rescue_rows[NROWS];
// codebook 2-way bf16 split, plain [split][code][dim]
__device__ __nv_bfloat16      g_cbs[2][KCB][DIM];

// ---------------- helpers ----------------
__device__ __forceinline__ uint32_t smem_u32(const void* p) {
    uint32_t a;
    asm("{ .reg .u64 t; cvta.to.shared.u64 t, %1; cvt.u32.u64 %0, t; }" : "=r"(a) : "l"(p));
    return a;
}
__device__ __forceinline__ void ldsm_x4(uint32_t* r, uint32_t a) {
    asm volatile("ldmatrix.sync.aligned.m8n8.x4.shared.b16 {%0,%1,%2,%3}, [%4];"
                 : "=r"(r[0]), "=r"(r[1]), "=r"(r[2]), "=r"(r[3]) : "r"(a));
}
__device__ __forceinline__ void mma16816(float* c, const uint32_t* a, const uint32_t* b) {
    asm volatile("mma.sync.aligned.m16n8k16.row.col.f32.bf16.bf16.f32 "
                 "{%0,%1,%2,%3}, {%4,%5,%6,%7}, {%8,%9}, {%0,%1,%2,%3};"
                 : "+f"(c[0]), "+f"(c[1]), "+f"(c[2]), "+f"(c[3])
                 : "r"(a[0]), "r"(a[1]), "r"(a[2]), "r"(a[3]), "r"(b[0]), "r"(b[1]));
}

// ---------------- prep: init + csum2 + codebook 2-way split ----------------
__global__ void __launch_bounds__(256) vq_prep(const float* __restrict__ cb) {
    int gid = blockIdx.x * 256 + threadIdx.x;          // grid 512 -> 131072
    {
        int k = gid >> 7, d = gid & 127;
        float x = cb[gid];
        __nv_bfloat16 b0 = __float2bfloat16(x);
        float r = x - __bfloat162float(b0);
        __nv_bfloat16 b1 = __float2bfloat16(r);
        g_cbs[0][k][d] = b0;
        g_cbs[1][k][d] = b1;
    }
    if (gid < 32768) {                                  // csum2, warp per code row
        int w = gid >> 5, l = gid & 31;
        float4 v = ((const float4*)cb)[w * 32 + l];
        float s = __fmul_rn(v.x, v.x);
        s = __fadd_rn(s, __fmul_rn(v.y, v.y));
        s = __fadd_rn(s, __fmul_rn(v.z, v.z));
        s = __fadd_rn(s, __fmul_rn(v.w, v.w));
        #pragma unroll
        for (int o = 16; o; o >>= 1) s += __shfl_xor_sync(0xffffffffu, s, o);
        if (l == 0) g_csum2[w] = s;
    }
    if (gid < KCB) g_counts[gid] = 0;
    if (gid == 0) { g_loss = 0.0; g_nrescue = 0; }
}

// ---------------- tensor main: HMMA mma.sync, 512 CTAs, 2/SM ---------------
// smem: A splits 2 x [128][136] bf16 (69632B) | B 2 x [64][136] bf16 (34816B)
//       | csum 1024 f32 (4096B)  => 108544B dynamic
#define A_SP   34816
#define SM_B   69632
#define B_SP   17408
#define SM_CS  104448
#define SMEMSZ 108544

#define UPD_L(d, i) { float _d = (d); \
    if (_d < m1l) { m2l = m1l; m1l = _d; i1l = (i); } else if (_d < m2l) m2l = _d; }
#define UPD_H(d, i) { float _d = (d); \
    if (_d < m1h) { m2h = m1h; m1h = _d; i1h = (i); } else if (_d < m2h) m2h = _d; }

__global__ void __launch_bounds__(256, 2)
vq_tc(const float* __restrict__ in) {
    extern __shared__ __align__(16) unsigned char sb[];
    const int tid  = threadIdx.x;
    const int lane = tid & 31;
    const int w    = tid >> 5;                      // 8 warps: rows w*16..w*16+15
    const int rowBase = blockIdx.x * 128;
    const uint32_t smem = smem_u32(sb);

    // csum -> smem
    for (int i = tid; i < KCB; i += 256)
        *(float*)(sb + SM_CS + i * 4) = g_csum2[i];

    // A tile: load f32, 2-way bf16 split into padded smem
    {
        const float* gin = in + (size_t)rowBase * DIM;
        #pragma unroll 8
        for (int i = 0; i < 64; i++) {
            int idx = i * 256 + tid;
            int m = idx >> 7, d = idx & 127;
            float x = gin[idx];
            __nv_bfloat16 b0 = __float2bfloat16(x);
            float r = x - __bfloat162float(b0);
            __nv_bfloat16 b1 = __float2bfloat16(r);
            *(__nv_bfloat16*)(sb + (m * 136 + d) * 2)        = b0;
            *(__nv_bfloat16*)(sb + A_SP + (m * 136 + d) * 2) = b1;
        }
    }
    __syncthreads();

    // A fragments, register-resident for the whole tile.
    // ldsm.x4 tiles: lanes0-7 m0-7/k0 | 8-15 m8-15/k0 | 16-23 m0-7/k8 | 24-31 m8-15/k8
    uint32_t af[2][8][4];
    {
        uint32_t rA = (uint32_t)(lane & 15);
        uint32_t k8 = (lane >= 16) ? 16u : 0u;
        uint32_t abase = smem + (uint32_t)(w * 16 + rA) * 272u + k8;
        #pragma unroll
        for (int s = 0; s < 2; s++)
            #pragma unroll
            for (int kt = 0; kt < 8; kt++)
                ldsm_x4(af[s][kt], abase + (uint32_t)s * A_SP + (uint32_t)kt * 32u);
    }

    // B ldsm base: pair of n-tiles per x4:
    // lanes0-7 n0-7/k0 | 8-15 n0-7/k8 | 16-23 n8-15/k0 | 24-31 n8-15/k8
    uint32_t rB = (uint32_t)((lane & 7) + ((lane >= 16) ? 8 : 0));
    uint32_t kB = (lane & 8) ? 16u : 0u;
    const uint32_t bbase = smem + SM_B + rB * 272u + kB;

    float m1l = 3.4e38f, m2l = 3.5e38f, m1h = 3.4e38f, m2h = 3.5e38f;
    int   i1l = 0, i1h = 0;

    const int PA[3] = {0, 0, 1};
    const int PB[3] = {0, 1, 0};

    for (int ch = 0; ch < NCHUNK; ch++) {
        __syncthreads();                            // prev chunk consumed
        #pragma unroll
        for (int j = 0; j < 8; j++) {               // B chunk, both splits
            int e  = j * 256 + tid;                 // 0..2047
            int sp = e >> 10, rr = (e >> 4) & 63, cc = e & 15;
            uint4 v = ((const uint4*)g_cbs[sp][ch * 64 + rr])[cc];
            *(uint4*)(sb + SM_B + sp * B_SP + rr * 272 + cc * 16) = v;
        }
        __syncthreads();

        #pragma unroll
        for (int np = 0; np < 4; np++) {            // n-tile pairs
            float c0[4] = {0, 0, 0, 0}, c1[4] = {0, 0, 0, 0};
            #pragma unroll
            for (int p = 0; p < 3; p++) {
                uint32_t bb = bbase + (uint32_t)PB[p] * B_SP + (uint32_t)np * 16u * 272u;
                #pragma unroll
                for (int kt = 0; kt < 8; kt++) {
                    uint32_t bf[4];
                    ldsm_x4(bf, bb + (uint32_t)kt * 32u);
                    mma16816(c0, af[PA[p]][kt], bf);
                    mma16816(c1, af[PA[p]][kt], bf + 2);
                }
            }
            // dists (rows2 omitted: constant per row, cancels in argmin/margins)
            int cb0 = ch * 64 + np * 16 + 2 * (lane & 3);
            int cb1 = cb0 + 8;
            float2 csA = *(float2*)(sb + SM_CS + cb0 * 4);
            float2 csB = *(float2*)(sb + SM_CS + cb1 * 4);
            UPD_L(fmaf(-2.0f, c0[0], csA.x), cb0);
            UPD_L(fmaf(-2.0f, c0[1], csA.y), cb0 + 1);
            UPD_H(fmaf(-2.0f, c0[2], csA.x), cb0);
            UPD_H(fmaf(-2.0f, c0[3], csA.y), cb0 + 1);
            UPD_L(fmaf(-2.0f, c1[0], csB.x), cb1);
            UPD_L(fmaf(-2.0f, c1[1], csB.y), cb1 + 1);
            UPD_H(fmaf(-2.0f, c1[2], csB.x), cb1);
            UPD_H(fmaf(-2.0f, c1[3], csB.y), cb1 + 1);
        }
    }

    // cross-lane (quad) lexicographic reduce of (m1,i1) and true second-min m2
    #pragma unroll
    for (int off = 1; off <= 2; off <<= 1) {
        float om1 = __shfl_xor_sync(0xffffffffu, m1l, off);
        float om2 = __shfl_xor_sync(0xffffffffu, m2l, off);
        int   oi1 = __shfl_xor_sync(0xffffffffu, i1l, off);
        float nm2 = fminf(fmaxf(m1l, om1), fminf(m2l, om2));
        if (om1 < m1l || (om1 == m1l && oi1 < i1l)) { m1l = om1; i1l = oi1; }
        m2l = nm2;
        om1 = __shfl_xor_sync(0xffffffffu, m1h, off);
        om2 = __shfl_xor_sync(0xffffffffu, m2h, off);
        oi1 = __shfl_xor_sync(0xffffffffu, i1h, off);
        nm2 = fminf(fmaxf(m1h, om1), fminf(m2h, om2));
        if (om1 < m1h || (om1 == m1h && oi1 < i1h)) { m1h = om1; i1h = oi1; }
        m2h = nm2;
    }
    if ((lane & 3) == 0) {
        int rlo = rowBase + w * 16 + (lane >> 2);
        int rhi = rlo + 8;
        g_best[rlo] = ((unsigned long long)__float_as_uint(m1l) << 32) | (unsigned int)i1l;
        g_best[rhi] = ((unsigned long long)__float_as_uint(m1h) << 32) | (unsigned int)i1h;
        if (m2l - m1l < TAU) { int s = atomicAdd(&g_nrescue, 1); g_rescue_rows[s] = rlo; }
        if (m2h - m1h < TAU) { int s = atomicAdd(&g_nrescue, 1); g_rescue_rows[s] = rhi; }
    }
}

// ---------------- rescue: exact fp32 recompute (bit-identical to R8 math) --
__global__ void __launch_bounds__(256)
vq_rescue(const float* __restrict__ in, const float* __restrict__ cb) {
    __shared__ float sx[128];
    __shared__ float srows2;
    __shared__ unsigned long long red[256];
    const int n = g_nrescue;
    for (int i = blockIdx.x; i < n; i += gridDim.x) {
        int row = g_rescue_rows[i];
        if (threadIdx.x < 128) sx[threadIdx.x] = in[(size_t)row * DIM + threadIdx.x];
        __syncthreads();
        if (threadIdx.x == 0) {
            float s = 0.0f;
            for (int d = 0; d < 128; d++) {
                float v = sx[d];
                s = __fadd_rn(s, __fmul_rn(v, v));
            }
            srows2 = s;
        }
        __syncthreads();
        unsigned long long best = 0xFFFFFFFFFFFFFFFFULL;
        #pragma unroll
        for (int q = 0; q < 4; q++) {
            int c = threadIdx.x * 4 + q;
            const float* cr = cb + (size_t)c * DIM;
            float se = 0.0f, so = 0.0f;
            for (int d = 0; d < 128; d += 2) {        // even/odd fused chains = R8
                se = fmaf(sx[d],     __ldg(&cr[d]),     se);
                so = fmaf(sx[d + 1], __ldg(&cr[d + 1]), so);
            }
            float dot  = __fadd_rn(se, so);
            float dist = __fsub_rn(__fadd_rn(srows2, g_csum2[c]), __fmul_rn(2.0f, dot));
            unsigned long long pk =
                ((unsigned long long)__float_as_uint(dist) << 32) | (unsigned int)c;
            if (pk < best) best = pk;
        }
        red[threadIdx.x] = best;
        __syncthreads();
        for (int s = 128; s; s >>= 1) {
            if (threadIdx.x < s && red[threadIdx.x + s] < red[threadIdx.x])
                red[threadIdx.x] = red[threadIdx.x + s];
            __syncthreads();
        }
        if (threadIdx.x == 0) g_best[row] = red[0];
        __syncthreads();
    }
}

// ---------------- output epilogue: warp per row (proven) -------------------
__global__ void __launch_bounds__(256)
vq_epi(const float* __restrict__ in, const float* __restrict__ cb,
       float* __restrict__ out) {
    __shared__ float blksum[8];
    const int tid = threadIdx.x;
    const int wid = tid >> 5, l = tid & 31;
    const int row = blockIdx.x * 8 + wid;

    const int bi = (int)(g_best[row] & 0xffffffffu);
    if (l == 0) atomicAdd(&g_counts[bi], 1);

    float4 q = ((const float4*)(cb + (size_t)bi  * DIM))[l];
    float4 x = ((const float4*)(in + (size_t)row * DIM))[l];
    float* outq = out + 1 + (size_t)row * DIM + l * 4;
    outq[0] = q.x; outq[1] = q.y; outq[2] = q.z; outq[3] = q.w;
    float d0 = x.x - q.x, d1 = x.y - q.y, d2 = x.z - q.z, d3 = x.w - q.w;
    float ls = d0 * d0;
    ls = fmaf(d1, d1, ls);
    ls = fmaf(d2, d2, ls);
    ls = fmaf(d3, d3, ls);
    #pragma unroll
    for (int o = 16; o; o >>= 1) ls += __shfl_xor_sync(0xffffffffu, ls, o);
    if (l == 0) blksum[wid] = ls;

    float2* enc = (float2*)(out + 2 + (size_t)NROWS * DIM) + (size_t)row * 512;
    #pragma unroll
    for (int k = 0; k < 16; k++) {
        int p = l + k * 32;
        int c0 = p * 2;
        float2 v;
        v.x = (c0     == bi) ? 1.0f : 0.0f;
        v.y = (c0 + 1 == bi) ? 1.0f : 0.0f;
        enc[p] = v;
    }

    __syncthreads();
    if (tid == 0) {
        double s = 0.0;
        #pragma unroll
        for (int i = 0; i < 8; i++) s += (double)blksum[i];
        atomicAdd(&g_loss, s);
    }
}

__global__ void vq_final(float* __restrict__ out) {
    __shared__ float sh[KCB];
    int t = threadIdx.x;
    float p = (float)g_counts[t] * (1.0f / 65536.0f);
    sh[t] = __fmul_rn(p, logf(__fadd_rn(p, 1e-10f)));
    __syncthreads();
    for (int s = 512; s; s >>= 1) {
        if (t < s) sh[t] += sh[t + s];
        __syncthreads();
    }
    if (t == 0) {
        out[1 + (size_t)NROWS * DIM] = expf(-sh[0]);
        double m = g_loss * (1.0 / ((double)NROWS * (double)DIM));
        out[0] = (float)(m + 0.25 * m);
    }
}

// ---------------- launch ----------------
extern "C" void kernel_launch(void* const* d_in, const int* in_sizes, int n_in,
                              void* d_out, int out_size) {
    const float* in = (const float*)d_in[0];
    const float* cb = (const float*)d_in[1];
    float* out = (float*)d_out;

    cudaFuncSetAttribute(vq_tc, cudaFuncAttributeMaxDynamicSharedMemorySize, SMEMSZ);

    vq_prep<<<512, 256>>>(cb);
    vq_tc<<<NTILES, 256, SMEMSZ>>>(in);
    vq_rescue<<<2048, 256>>>(in, cb);
    vq_epi<<<8192, 256>>>(in, cb, out);
    vq_final<<<1, 1024>>>(out);
}

// round 15
// speedup vs baseline: 3.3676x; 3.3676x over previous
#include <cuda_runtime.h>
#include <cuda_bf16.h>
#include <cstdint>

#define NROWS  65536
#define DIM    128
#define KCB    1024
#define NCHUNK 16
#define NTILES 512
#define TAU    6.0e-5f

// ---------------- device scratch (no allocations allowed) ----------------
__device__ float              g_csum2[KCB];
__device__ int                g_counts[KCB];
__device__ double             g_loss;
__device__ unsigned long long g_best[NROWS];
__device__ int                g_nrescue;
__device__ int                g_rescue_rows[NROWS];
// codebook 2-way bf16 split, plain [split][code][dim]
__device__ __nv_bfloat16      g_cbs[2][KCB][DIM];

// ---------------- helpers ----------------
__device__ __forceinline__ uint32_t smem_u32(const void* p) {
    uint32_t a;
    asm("{ .reg .u64 t; cvta.to.shared.u64 t, %1; cvt.u32.u64 %0, t; }" : "=r"(a) : "l"(p));
    return a;
}
__device__ __forceinline__ void ldsm_x4(uint32_t* r, uint32_t a) {
    asm volatile("ldmatrix.sync.aligned.m8n8.x4.shared.b16 {%0,%1,%2,%3}, [%4];"
                 : "=r"(r[0]), "=r"(r[1]), "=r"(r[2]), "=r"(r[3]) : "r"(a));
}
__device__ __forceinline__ void mma16816(float* c, const uint32_t* a, const uint32_t* b) {
    asm volatile("mma.sync.aligned.m16n8k16.row.col.f32.bf16.bf16.f32 "
                 "{%0,%1,%2,%3}, {%4,%5,%6,%7}, {%8,%9}, {%0,%1,%2,%3};"
                 : "+f"(c[0]), "+f"(c[1]), "+f"(c[2]), "+f"(c[3])
                 : "r"(a[0]), "r"(a[1]), "r"(a[2]), "r"(a[3]), "r"(b[0]), "r"(b[1]));
}
__device__ __forceinline__ unsigned long long ffma2(unsigned long long a,
                                                    unsigned long long b,
                                                    unsigned long long c) {
    unsigned long long d;
    asm("fma.rn.f32x2 %0, %1, %2, %3;" : "=l"(d) : "l"(a), "l"(b), "l"(c));
    return d;
}
__device__ __forceinline__ float2 u2f2(unsigned long long v) {
    union { unsigned long long u; float2 f; } cvt;
    cvt.u = v;
    return cvt.f;
}

// ---------------- prep: init + csum2 + codebook 2-way split ----------------
__global__ void __launch_bounds__(256) vq_prep(const float* __restrict__ cb) {
    int gid = blockIdx.x * 256 + threadIdx.x;          // grid 512 -> 131072
    {
        int k = gid >> 7, d = gid & 127;
        float x = cb[gid];
        __nv_bfloat16 b0 = __float2bfloat16(x);
        float r = x - __bfloat162float(b0);
        __nv_bfloat16 b1 = __float2bfloat16(r);
        g_cbs[0][k][d] = b0;
        g_cbs[1][k][d] = b1;
    }
    if (gid < 32768) {                                  // csum2, warp per code row
        int w = gid >> 5, l = gid & 31;
        float4 v = ((const float4*)cb)[w * 32 + l];
        float s = __fmul_rn(v.x, v.x);
        s = __fadd_rn(s, __fmul_rn(v.y, v.y));
        s = __fadd_rn(s, __fmul_rn(v.z, v.z));
        s = __fadd_rn(s, __fmul_rn(v.w, v.w));
        #pragma unroll
        for (int o = 16; o; o >>= 1) s += __shfl_xor_sync(0xffffffffu, s, o);
        if (l == 0) g_csum2[w] = s;
    }
    if (gid < KCB) g_counts[gid] = 0;
    if (gid == 0) { g_loss = 0.0; g_nrescue = 0; }
}

// ---------------- tensor main: HMMA mma.sync, 512 CTAs, 2/SM ---------------
// smem: A splits 2 x [128][136] bf16 | B 2 x [64][136] bf16 | csum 1024 f32
#define A_SP   34816
#define SM_B   69632
#define B_SP   17408
#define SM_CS  104448
#define SMEMSZ 108544

#define UPD_L(d, i) { float _d = (d); \
    if (_d < m1l) { m2l = m1l; m1l = _d; i1l = (i); } else if (_d < m2l) m2l = _d; }
#define UPD_H(d, i) { float _d = (d); \
    if (_d < m1h) { m2h = m1h; m1h = _d; i1h = (i); } else if (_d < m2h) m2h = _d; }

__global__ void __launch_bounds__(256, 2)
vq_tc(const float* __restrict__ in) {
    extern __shared__ __align__(16) unsigned char sb[];
    const int tid  = threadIdx.x;
    const int lane = tid & 31;
    const int w    = tid >> 5;                      // 8 warps: rows w*16..w*16+15
    const int rowBase = blockIdx.x * 128;
    const uint32_t smem = smem_u32(sb);

    for (int i = tid; i < KCB; i += 256)
        *(float*)(sb + SM_CS + i * 4) = g_csum2[i];

    // A tile: load f32, 2-way bf16 split into padded smem
    {
        const float* gin = in + (size_t)rowBase * DIM;
        #pragma unroll 8
        for (int i = 0; i < 64; i++) {
            int idx = i * 256 + tid;
            int m = idx >> 7, d = idx & 127;
            float x = gin[idx];
            __nv_bfloat16 b0 = __float2bfloat16(x);
            float r = x - __bfloat162float(b0);
            __nv_bfloat16 b1 = __float2bfloat16(r);
            *(__nv_bfloat16*)(sb + (m * 136 + d) * 2)        = b0;
            *(__nv_bfloat16*)(sb + A_SP + (m * 136 + d) * 2) = b1;
        }
    }

    // ldsm bases (mapping identical to R14 — functionally proven)
    uint32_t rA = (uint32_t)(lane & 15);
    uint32_t k8 = (lane >= 16) ? 16u : 0u;
    const uint32_t abase = smem + (uint32_t)(w * 16 + rA) * 272u + k8;
    uint32_t rB = (uint32_t)((lane & 7) + ((lane >= 16) ? 8 : 0));
    uint32_t kB = (lane & 8) ? 16u : 0u;
    const uint32_t bbase = smem + SM_B + rB * 272u + kB;

    float m1l = 3.4e38f, m2l = 3.5e38f, m1h = 3.4e38f, m2h = 3.5e38f;
    int   i1l = 0, i1h = 0;

    for (int ch = 0; ch < NCHUNK; ch++) {
        __syncthreads();                            // prev chunk consumed / A done
        #pragma unroll
        for (int j = 0; j < 8; j++) {               // B chunk, both splits
            int e  = j * 256 + tid;                 // 0..2047
            int sp = e >> 10, rr = (e >> 4) & 63, cc = e & 15;
            uint4 v = ((const uint4*)g_cbs[sp][ch * 64 + rr])[cc];
            *(uint4*)(sb + SM_B + sp * B_SP + rr * 272 + cc * 16) = v;
        }
        __syncthreads();

        // per-chunk accumulators: acc[np][0..3]=rows g, cols n..; [4..7]=+8 cols
        float acc[4][8];
        #pragma unroll
        for (int np = 0; np < 4; np++)
            #pragma unroll
            for (int q = 0; q < 8; q++) acc[np][q] = 0.0f;

        // products: a0*b0, a0*b1, a1*b0 (a1*b1 omitted, <=6e-7 effect)
        #pragma unroll
        for (int p = 0; p < 3; p++) {
            const int pa = (p == 2) ? 1 : 0;
            const int pb = (p == 1) ? 1 : 0;
            uint32_t af[8][4];                      // one split only: 32 regs
            #pragma unroll
            for (int kt = 0; kt < 8; kt++)
                ldsm_x4(af[kt], abase + (uint32_t)pa * A_SP + (uint32_t)kt * 32u);
            #pragma unroll
            for (int np = 0; np < 4; np++) {
                uint32_t bb = bbase + (uint32_t)pb * B_SP + (uint32_t)np * 16u * 272u;
                #pragma unroll
                for (int kt = 0; kt < 8; kt++) {
                    uint32_t bf[4];
                    ldsm_x4(bf, bb + (uint32_t)kt * 32u);
                    mma16816(acc[np],     af[kt], bf);
                    mma16816(acc[np] + 4, af[kt], bf + 2);
                }
            }
        }

        // dists (rows2 omitted: per-row constant, cancels in argmin/margins)
        #pragma unroll
        for (int np = 0; np < 4; np++) {
            int cb0 = ch * 64 + np * 16 + 2 * (lane & 3);
            int cb1 = cb0 + 8;
            float2 csA = *(float2*)(sb + SM_CS + cb0 * 4);
            float2 csB = *(float2*)(sb + SM_CS + cb1 * 4);
            UPD_L(fmaf(-2.0f, acc[np][0], csA.x), cb0);
            UPD_L(fmaf(-2.0f, acc[np][1], csA.y), cb0 + 1);
            UPD_H(fmaf(-2.0f, acc[np][2], csA.x), cb0);
            UPD_H(fmaf(-2.0f, acc[np][3], csA.y), cb0 + 1);
            UPD_L(fmaf(-2.0f, acc[np][4], csB.x), cb1);
            UPD_L(fmaf(-2.0f, acc[np][5], csB.y), cb1 + 1);
            UPD_H(fmaf(-2.0f, acc[np][6], csB.x), cb1);
            UPD_H(fmaf(-2.0f, acc[np][7], csB.y), cb1 + 1);
        }
    }

    // cross-lane (quad) lexicographic reduce of (m1,i1) and true second-min
    #pragma unroll
    for (int off = 1; off <= 2; off <<= 1) {
        float om1 = __shfl_xor_sync(0xffffffffu, m1l, off);
        float om2 = __shfl_xor_sync(0xffffffffu, m2l, off);
        int   oi1 = __shfl_xor_sync(0xffffffffu, i1l, off);
        float nm2 = fminf(fmaxf(m1l, om1), fminf(m2l, om2));
        if (om1 < m1l || (om1 == m1l && oi1 < i1l)) { m1l = om1; i1l = oi1; }
        m2l = nm2;
        om1 = __shfl_xor_sync(0xffffffffu, m1h, off);
        om2 = __shfl_xor_sync(0xffffffffu, m2h, off);
        oi1 = __shfl_xor_sync(0xffffffffu, i1h, off);
        nm2 = fminf(fmaxf(m1h, om1), fminf(m2h, om2));
        if (om1 < m1h || (om1 == m1h && oi1 < i1h)) { m1h = om1; i1h = oi1; }
        m2h = nm2;
    }
    if ((lane & 3) == 0) {
        int rlo = rowBase + w * 16 + (lane >> 2);
        int rhi = rlo + 8;
        g_best[rlo] = ((unsigned long long)__float_as_uint(m1l) << 32) | (unsigned int)i1l;
        g_best[rhi] = ((unsigned long long)__float_as_uint(m1h) << 32) | (unsigned int)i1h;
        if (m2l - m1l < TAU) { int s = atomicAdd(&g_nrescue, 1); g_rescue_rows[s] = rlo; }
        if (m2h - m1h < TAU) { int s = atomicAdd(&g_nrescue, 1); g_rescue_rows[s] = rhi; }
    }
}

// ---------------- rescue: R8-proven tile kernel over gathered rows ---------
#define B_STRIDE 132

__global__ void __launch_bounds__(256)
vq_rescue(const float* __restrict__ in, const float* __restrict__ cb) {
    extern __shared__ float smem[];
    float* As      = smem;                          // 128*128
    float* Bs      = smem + 128 * 128;              // 64*132 (reused for reduce)
    float* rows2_s = Bs + 64 * B_STRIDE;            // 128
    float* csum_s  = rows2_s + 128;                 // 64
    int*   rid_s   = (int*)(csum_s + 64);           // 128
    float* redv    = Bs;
    int*   redi    = (int*)(Bs + 128 * 16);

    const int tid = threadIdx.x;
    const int tx  = tid & 15;
    const int ty  = tid >> 4;
    const int n   = g_nrescue;
    const int ntiles = (n + 127) >> 7;

    for (int t = blockIdx.x; t < ntiles; t += gridDim.x) {
        __syncthreads();
        if (tid < 128) {
            int idx = t * 128 + tid;
            rid_s[tid] = g_rescue_rows[idx < n ? idx : (n - 1)];
        }
        __syncthreads();
        {   // gather A rows (row-contiguous float4)
            float4* As4 = (float4*)As;
            #pragma unroll
            for (int i = 0; i < 16; i++) {
                int idx = tid + i * 256;
                int r = idx >> 5, c = idx & 31;
                As4[r * 32 + c] = ((const float4*)(in + (size_t)rid_s[r] * DIM))[c];
            }
        }
        __syncthreads();
        if (tid < 128) {
            float s = 0.0f;
            const float* ar = As + tid * 128;
            for (int d = 0; d < DIM; d++) {
                float v = ar[d];
                s = __fadd_rn(s, __fmul_rn(v, v));
            }
            rows2_s[tid] = s;
        }

        float minv[8];
        int   mini[8];
        #pragma unroll
        for (int r = 0; r < 8; r++) { minv[r] = 3.4e38f; mini[r] = 0x7fffffff; }

        for (int ch = 0; ch < NCHUNK; ch++) {
            __syncthreads();
            {
                const float4* gb = (const float4*)(cb + (size_t)ch * 64 * DIM);
                #pragma unroll
                for (int i = 0; i < 8; i++) {
                    int idx = tid + i * 256;
                    int r = idx >> 5, c = idx & 31;
                    ((float4*)(Bs + r * B_STRIDE))[c] = gb[idx];
                }
                if (tid < 64) csum_s[tid] = g_csum2[ch * 64 + tid];
            }
            __syncthreads();

            unsigned long long acc[8][4];
            #pragma unroll
            for (int r = 0; r < 8; r++)
                #pragma unroll
                for (int j = 0; j < 4; j++) acc[r][j] = 0ULL;

            const ulonglong2* A2 = (const ulonglong2*)As + (size_t)(ty * 8) * 32;
            const ulonglong2* B2 = (const ulonglong2*)Bs;

            #pragma unroll 4
            for (int dq = 0; dq < 32; dq++) {
                ulonglong2 b[4];
                #pragma unroll
                for (int j = 0; j < 4; j++)
                    b[j] = B2[(tx + 16 * j) * 33 + dq];
                #pragma unroll
                for (int r = 0; r < 8; r++) {
                    ulonglong2 a = A2[r * 32 + dq];
                    #pragma unroll
                    for (int j = 0; j < 4; j++) {
                        acc[r][j] = ffma2(a.x, b[j].x, acc[r][j]);
                        acc[r][j] = ffma2(a.y, b[j].y, acc[r][j]);
                    }
                }
            }

            #pragma unroll
            for (int r = 0; r < 8; r++) {
                float tt = rows2_s[ty * 8 + r];
                #pragma unroll
                for (int j = 0; j < 4; j++) {
                    float2 s = u2f2(acc[r][j]);
                    float dot = __fadd_rn(s.x, s.y);
                    float dist = __fsub_rn(__fadd_rn(tt, csum_s[tx + 16 * j]),
                                           __fmul_rn(2.0f, dot));
                    int cod = ch * 64 + tx + 16 * j;
                    if (dist < minv[r]) { minv[r] = dist; mini[r] = cod; }
                }
            }
        }

        __syncthreads();
        #pragma unroll
        for (int r = 0; r < 8; r++) {
            int lr = ty * 8 + r;
            redv[lr * 16 + tx] = minv[r];
            redi[lr * 16 + tx] = mini[r];
        }
        __syncthreads();
        if (tid < 128 && t * 128 + tid < n) {
            float bv = 3.5e38f;
            int   bi = 0x7fffffff;
            #pragma unroll
            for (int t2 = 0; t2 < 16; t2++) {
                float v = redv[tid * 16 + t2];
                int   i2 = redi[tid * 16 + t2];
                if (v < bv || (v == bv && i2 < bi)) { bv = v; bi = i2; }
            }
            g_best[rid_s[tid]] =
                ((unsigned long long)__float_as_uint(bv) << 32) | (unsigned int)bi;
        }
    }
}

// ---------------- output epilogue: warp per row (proven) -------------------
__global__ void __launch_bounds__(256)
vq_epi(const float* __restrict__ in, const float* __restrict__ cb,
       float* __restrict__ out) {
    __shared__ float blksum[8];
    const int tid = threadIdx.x;
    const int wid = tid >> 5, l = tid & 31;
    const int row = blockIdx.x * 8 + wid;

    const int bi = (int)(g_best[row] & 0xffffffffu);
    if (l == 0) atomicAdd(&g_counts[bi], 1);

    float4 q = ((const float4*)(cb + (size_t)bi  * DIM))[l];
    float4 x = ((const float4*)(in + (size_t)row * DIM))[l];
    float* outq = out + 1 + (size_t)row * DIM + l * 4;
    outq[0] = q.x; outq[1] = q.y; outq[2] = q.z; outq[3] = q.w;
    float d0 = x.x - q.x, d1 = x.y - q.y, d2 = x.z - q.z, d3 = x.w - q.w;
    float ls = d0 * d0;
    ls = fmaf(d1, d1, ls);
    ls = fmaf(d2, d2, ls);
    ls = fmaf(d3, d3, ls);
    #pragma unroll
    for (int o = 16; o; o >>= 1) ls += __shfl_xor_sync(0xffffffffu, ls, o);
    if (l == 0) blksum[wid] = ls;

    float2* enc = (float2*)(out + 2 + (size_t)NROWS * DIM) + (size_t)row * 512;
    #pragma unroll
    for (int k = 0; k < 16; k++) {
        int p = l + k * 32;
        int c0 = p * 2;
        float2 v;
        v.x = (c0     == bi) ? 1.0f : 0.0f;
        v.y = (c0 + 1 == bi) ? 1.0f : 0.0f;
        enc[p] = v;
    }

    __syncthreads();
    if (tid == 0) {
        double s = 0.0;
        #pragma unroll
        for (int i = 0; i < 8; i++) s += (double)blksum[i];
        atomicAdd(&g_loss, s);
    }
}

__global__ void vq_final(float* __restrict__ out) {
    __shared__ float sh[KCB];
    int t = threadIdx.x;
    float p = (float)g_counts[t] * (1.0f / 65536.0f);
    sh[t] = __fmul_rn(p, logf(__fadd_rn(p, 1e-10f)));
    __syncthreads();
    for (int s = 512; s; s >>= 1) {
        if (t < s) sh[t] += sh[t + s];
        __syncthreads();
    }
    if (t == 0) {
        out[1 + (size_t)NROWS * DIM] = expf(-sh[0]);
        double m = g_loss * (1.0 / ((double)NROWS * (double)DIM));
        out[0] = (float)(m + 0.25 * m);
    }
}

// ---------------- launch ----------------
extern "C" void kernel_launch(void* const* d_in, const int* in_sizes, int n_in,
                              void* d_out, int out_size) {
    const float* in = (const float*)d_in[0];
    const float* cb = (const float*)d_in[1];
    float* out = (float*)d_out;

    cudaFuncSetAttribute(vq_tc, cudaFuncAttributeMaxDynamicSharedMemorySize, SMEMSZ);
    const int RSMEM = (128 * 128 + 64 * B_STRIDE + 128 + 64 + 128) * 4;
    cudaFuncSetAttribute(vq_rescue, cudaFuncAttributeMaxDynamicSharedMemorySize, RSMEM);

    vq_prep<<<512, 256>>>(cb);
    vq_tc<<<NTILES, 256, SMEMSZ>>>(in);
    vq_rescue<<<64, 256, RSMEM>>>(in, cb);
    vq_epi<<<8192, 256>>>(in, cb, out);
    vq_final<<<1, 1024>>>(out);
}